// round 3
// baseline (speedup 1.0000x reference)
#include <cuda_runtime.h>
#include <math.h>

#define NBLK 148
#define BN   8000
#define TT   128
typedef unsigned long long ull;

// ---------- static device scratch ----------
__device__ float g_xT[TT * BN];
__device__ float g_mT[TT * BN];
__device__ float g_M4[2000 * 500];   // Af, Af^2, Ab, Ab^2
__device__ float g_M2[1000 * 500];   // Af, Ab
__device__ float g_h[64 * BN];
__device__ float g_xin[64 * BN];
__device__ float g_Ddec[128 * BN];
__device__ float g_rh[64 * BN];
__device__ float g_u[64 * BN];
__device__ float g_Dgd[264 * BN];
__device__ float g_Dcd[264 * BN];
__device__ float g_x1[BN];
__device__ float g_x2[BN];
__device__ float g_Wru[128 * 330];
__device__ float g_Wp[64 * 192];
__device__ float g_bru[128];
__device__ float g_bp[64];
__device__ unsigned g_cnt;
__device__ volatile unsigned g_gen;

// ---------- f32x2 helpers ----------
__device__ __forceinline__ ull splat2(float x) {
    ull r; asm("mov.b64 %0,{%1,%1};" : "=l"(r) : "f"(x)); return r;
}
__device__ __forceinline__ void ffma2(ull& d, ull a, ull b) {
    asm("fma.rn.f32x2 %0,%1,%2,%3;" : "=l"(d) : "l"(a), "l"(b), "l"(d));
}
__device__ __forceinline__ float2 unpk(ull p) {
    float2 v; asm("mov.b64 {%0,%1},%2;" : "=f"(v.x), "=f"(v.y) : "l"(p)); return v;
}

// ---------- software grid barrier ----------
__device__ __forceinline__ void gsync() {
    __syncthreads();
    if (threadIdx.x == 0) {
        __threadfence();
        unsigned gen = g_gen;
        if (atomicAdd(&g_cnt, 1u) == NBLK - 1) {
            atomicExch(&g_cnt, 0u);
            __threadfence();
            g_gen = gen + 1;
        } else {
            while (g_gen == gen) __nanosleep(32);
        }
        __threadfence();   // IVALL: invalidate this SM's L1 before CTA proceeds
    }
    __syncthreads();
}

// ---------- conv input channel dispatch ----------
template <int KIND>
__device__ __forceinline__ const float* conv_in(int k, int t) {
    if (KIND == 0) {                       // [x1, mf, h]  K=66
        if (k == 0) return g_x1;
        if (k == 1) return g_mT + t * BN;
        return g_h + (k - 2) * BN;
    } else if (KIND == 1) {                // [Ddec(128), h]  K=192
        return (k < 128) ? g_Ddec + k * BN : g_h + (k - 128) * BN;
    } else if (KIND == 2) {                // [x2, mf, h, Dgd]  K=330
        if (k == 0) return g_x2;
        if (k == 1) return g_mT + t * BN;
        if (k < 66) return g_h + (k - 2) * BN;
        return g_Dgd + (k - 66) * BN;
    } else {                               // [x2, mf, rh, Dcd]  K=330
        if (k == 0) return g_x2;
        if (k == 1) return g_mT + t * BN;
        if (k < 66) return g_rh + (k - 2) * BN;
        return g_Dcd + (k - 66) * BN;
    }
}

// ---------- fused stage B (after W_p tile; out tile in sm_out) ----------
__device__ __forceinline__ void stageB_tile(int t, int n0, float* sm, const float* sm_out,
        const float* __restrict__ Wro, const float* __restrict__ bro,
        float* __restrict__ imp, float* __restrict__ reps) {
    int tid = threadIdx.x;
    __syncthreads();
    if (tid < 128) sm[tid] = __ldg(Wro + tid);
    __syncthreads();
    if (tid < 128) {
        int bn = n0 + tid;
        if (bn < BN) {
            float acc = __ldg(bro);
            int b = bn / 500, n = bn - b * 500;
            int rbase = (b * 128 * 500 + n) * 128 + t;
#pragma unroll 4
            for (int c = 0; c < 64; c++) {
                float ov = sm_out[c * 128 + tid];
                float hv = g_h[c * BN + bn];
                acc += sm[c] * ov + sm[64 + c] * hv;
                reps[rbase + c * 64000] = ov;
                reps[rbase + (64 + c) * 64000] = hv;
            }
            imp[bn * TT + t] = acc;
            float m = g_mT[t * BN + bn];
            g_x2[bn] = (m > 0.5f) ? g_x1[bn] : acc;
        }
    }
}

// ---------- fused stage A for t=tn (new-h tile in sm_out) ----------
__device__ __forceinline__ void stageA_tile(int tn, int n0, float* sm, const float* sm_out,
        const float* __restrict__ Wfs, const float* __restrict__ bfs,
        float* __restrict__ pred) {
    int tid = threadIdx.x;
    __syncthreads();
    if (tid < 64) sm[tid] = __ldg(Wfs + tid);
    __syncthreads();
    if (tid < 128) {
        int bn = n0 + tid;
        if (bn < BN) {
            float acc = __ldg(bfs);
#pragma unroll 8
            for (int c = 0; c < 64; c++) acc += sm[c] * sm_out[c * 128 + tid];
            pred[bn * TT + tn] = acc;
            float m = g_mT[tn * BN + bn];
            g_x1[bn] = (m > 0.5f) ? g_xT[tn * BN + bn] : acc;
        }
    }
}

// ---------- conv GEMM stage (O x 8000), fused epilogues ----------
// EPI 0:->g_xin  1: prelu->sm_out + stageB  2: sigmoid->rh/u  3: tanh+GRU->h + stageA
template <int KIND, int EPI>
__device__ __forceinline__ void conv_stage(int t,
        const float* __restrict__ Wg, const float* __restrict__ bias,
        float* sm, float* sm_out,
        const float* Wro, const float* bro,
        const float* Wfs, const float* bfs, const float* pa,
        float* imp, float* pred, float* reps) {
    constexpr int K = (KIND == 0) ? 66 : (KIND == 1) ? 192 : 330;
    constexpr int NOROW = (KIND == 2) ? 2 : 1;
    float* Ws = sm;            // [8][68]
    float* Is = sm + 8 * 68;   // [8][132]
    const int tid = threadIdx.x;
    for (int tile = blockIdx.x; tile < NOROW * 63; tile += NBLK) {
        const int o0 = (tile / 63) * 64;
        const int n0 = (tile % 63) * 128;
        const int rg = (tid >> 4) * 4;
        const int cg = (tid & 15) * 8;
        ull acc[4][4];
#pragma unroll
        for (int i = 0; i < 4; i++)
#pragma unroll
            for (int j = 0; j < 4; j++) acc[i][j] = 0ull;

        float wv0, wv1; float4 iv;
        {
            int e0 = tid, e1 = tid + 256;
            int kg0 = e0 & 7, kg1 = e1 & 7;
            wv0 = (kg0 < K) ? __ldg(Wg + (o0 + (e0 >> 3)) * K + kg0) : 0.f;
            wv1 = (kg1 < K) ? __ldg(Wg + (o0 + (e1 >> 3)) * K + kg1) : 0.f;
            int kk = tid >> 5, j4 = (tid & 31) * 4, col = n0 + j4;
            iv = make_float4(0.f, 0.f, 0.f, 0.f);
            if (kk < K && col < BN) iv = *(const float4*)(conv_in<KIND>(kk, t) + col);
        }
        for (int k0 = 0; k0 < K; k0 += 8) {
            __syncthreads();
            {
                int e0 = tid, e1 = tid + 256;
                Ws[(e0 & 7) * 68 + (e0 >> 3)] = wv0;
                Ws[(e1 & 7) * 68 + (e1 >> 3)] = wv1;
                int kk = tid >> 5, j4 = (tid & 31) * 4;
                *(float4*)&Is[kk * 132 + j4] = iv;
            }
            __syncthreads();
            if (k0 + 8 < K) {
                int e0 = tid, e1 = tid + 256;
                int kg0 = k0 + 8 + (e0 & 7), kg1 = k0 + 8 + (e1 & 7);
                wv0 = (kg0 < K) ? __ldg(Wg + (o0 + (e0 >> 3)) * K + kg0) : 0.f;
                wv1 = (kg1 < K) ? __ldg(Wg + (o0 + (e1 >> 3)) * K + kg1) : 0.f;
                int kk = tid >> 5, j4 = (tid & 31) * 4, col = n0 + j4;
                int kg = k0 + 8 + kk;
                iv = make_float4(0.f, 0.f, 0.f, 0.f);
                if (kg < K && col < BN) iv = *(const float4*)(conv_in<KIND>(kg, t) + col);
            }
#pragma unroll
            for (int kk = 0; kk < 8; kk++) {
                float4 a = *(const float4*)&Ws[kk * 68 + rg];
                ull av0 = splat2(a.x), av1 = splat2(a.y), av2 = splat2(a.z), av3 = splat2(a.w);
                ulonglong2 q0 = ((const ulonglong2*)&Is[kk * 132 + cg])[0];
                ulonglong2 q1 = ((const ulonglong2*)&Is[kk * 132 + cg])[1];
                ffma2(acc[0][0], av0, q0.x); ffma2(acc[0][1], av0, q0.y);
                ffma2(acc[0][2], av0, q1.x); ffma2(acc[0][3], av0, q1.y);
                ffma2(acc[1][0], av1, q0.x); ffma2(acc[1][1], av1, q0.y);
                ffma2(acc[1][2], av1, q1.x); ffma2(acc[1][3], av1, q1.y);
                ffma2(acc[2][0], av2, q0.x); ffma2(acc[2][1], av2, q0.y);
                ffma2(acc[2][2], av2, q1.x); ffma2(acc[2][3], av2, q1.y);
                ffma2(acc[3][0], av3, q0.x); ffma2(acc[3][1], av3, q0.y);
                ffma2(acc[3][2], av3, q1.x); ffma2(acc[3][3], av3, q1.y);
            }
        }
        float paval = (EPI == 1) ? __ldg(pa) : 0.f;
#pragma unroll
        for (int i = 0; i < 4; i++) {
            int o = o0 + rg + i;
            float bs = __ldg(bias + o);
#pragma unroll
            for (int j2 = 0; j2 < 4; j2++) {
                float2 v2 = unpk(acc[i][j2]);
#pragma unroll
                for (int e = 0; e < 2; e++) {
                    int bn = n0 + cg + 2 * j2 + e;
                    if (bn >= BN) continue;
                    float v = ((e == 0) ? v2.x : v2.y) + bs;
                    if (EPI == 0) {
                        g_xin[o * BN + bn] = v;
                    } else if (EPI == 1) {
                        sm_out[o * 128 + (bn - n0)] = (v >= 0.f) ? v : paval * v;
                    } else if (EPI == 2) {
                        float sv = 1.f / (1.f + expf(-v));
                        if (o < 64) g_rh[o * BN + bn] = sv * g_h[o * BN + bn];
                        else        g_u[(o - 64) * BN + bn] = sv;
                    } else {
                        float cv = tanhf(v);
                        int id = o * BN + bn;
                        float uu = g_u[id];
                        float hn = uu * g_h[id] + (1.f - uu) * cv;
                        g_h[id] = hn;
                        sm_out[o * 128 + (bn - n0)] = hn;
                    }
                }
            }
        }
        if (EPI == 1) stageB_tile(t, n0, sm, sm_out, Wro, bro, imp, reps);
        if (EPI == 3 && t + 1 < TT) stageA_tile(t + 1, n0, sm, sm_out, Wfs, bfs, pred);
    }
}

// ---------- diffusion GEMM: rows x Ncols, K=500 ----------
// KIND 0: X=g_xin (M=1024), B=g_M2, N=1000 -> g_Ddec
// KIND 1: X=[x2,mf,h] (M=1056), B=g_M4, N=2000 -> g_Dgd
// KIND 2: X=[x2,mf,rh] -> g_Dcd
template <int KIND, int TN>
__device__ __forceinline__ void diff_stage(int t, float* sm) {
    constexpr int M   = (KIND == 0) ? 1024 : 1056;
    constexpr int NC  = (KIND == 0) ? 1000 : 2000;
    constexpr int CCH = (KIND == 0) ? 64 : 66;
    constexpr int BC  = TN * 16;
    constexpr int TM  = (M + 127) / 128;
    constexpr int TNC = (NC + BC - 1) / BC;
    const float* Bm = (KIND == 0) ? g_M2 : g_M4;
    float* Out = (KIND == 0) ? g_Ddec : ((KIND == 1) ? g_Dgd : g_Dcd);
    float* Xs = sm;            // [8][132]
    float* Bs = sm + 8 * 132;
    const int tid = threadIdx.x;
    for (int tile = blockIdx.x; tile < TM * TNC; tile += NBLK) {
        const int m0 = (tile / TNC) * 128;
        const int n0 = (tile % TNC) * BC;
        const int lr = tid >> 1, lk = (tid & 1) * 4;
        const float* xrow = nullptr;
        {
            int gr = m0 + lr;
            if (gr < M) {
                if (KIND == 0) {
                    xrow = g_xin + gr * 500;   // [c][b][n] == gr*500
                } else {
                    int c = gr >> 4, b = gr & 15;
                    const float* base = (c == 0) ? g_x2
                                       : (c == 1) ? (g_mT + t * BN)
                                       : (((KIND == 1) ? g_h : g_rh) + (c - 2) * BN);
                    xrow = base + b * 500;
                }
            }
        }
        const float* brow = nullptr;
        if (lr < BC) { int gc = n0 + lr; if (gc < NC) brow = Bm + gc * 500; }
        const int tr = (tid >> 4) * 8;
        const int tc = (tid & 15) * TN;
        ull acc[8][TN / 2];
#pragma unroll
        for (int i = 0; i < 8; i++)
#pragma unroll
            for (int j = 0; j < TN / 2; j++) acc[i][j] = 0ull;

        float4 xv = make_float4(0.f, 0.f, 0.f, 0.f), bv = xv;
        if (xrow) xv = *(const float4*)(xrow + lk);
        if (brow) bv = *(const float4*)(brow + lk);
        for (int k0 = 0; k0 < 500; k0 += 8) {
            __syncthreads();
            Xs[(lk + 0) * 132 + lr] = xv.x; Xs[(lk + 1) * 132 + lr] = xv.y;
            Xs[(lk + 2) * 132 + lr] = xv.z; Xs[(lk + 3) * 132 + lr] = xv.w;
            if (lr < BC) {
                Bs[(lk + 0) * 132 + lr] = bv.x; Bs[(lk + 1) * 132 + lr] = bv.y;
                Bs[(lk + 2) * 132 + lr] = bv.z; Bs[(lk + 3) * 132 + lr] = bv.w;
            }
            __syncthreads();
            if (k0 + 8 < 500) {
                int kn = k0 + 8 + lk;
                xv = make_float4(0.f, 0.f, 0.f, 0.f); bv = xv;
                if (xrow && kn < 500) {
                    if (kn + 3 < 500) xv = *(const float4*)(xrow + kn);
                    else { xv.x = xrow[kn]; if (kn+1<500) xv.y = xrow[kn+1];
                           if (kn+2<500) xv.z = xrow[kn+2]; }
                }
                if (brow && kn < 500) {
                    if (kn + 3 < 500) bv = *(const float4*)(brow + kn);
                    else { bv.x = brow[kn]; if (kn+1<500) bv.y = brow[kn+1];
                           if (kn+2<500) bv.z = brow[kn+2]; }
                }
            }
#pragma unroll
            for (int kk = 0; kk < 8; kk++) {
                float4 a0 = *(const float4*)&Xs[kk * 132 + tr];
                float4 a1 = *(const float4*)&Xs[kk * 132 + tr + 4];
                ull av[8] = {splat2(a0.x), splat2(a0.y), splat2(a0.z), splat2(a0.w),
                             splat2(a1.x), splat2(a1.y), splat2(a1.z), splat2(a1.w)};
                ull bvv[TN / 2];
                {
                    ulonglong2 q0 = ((const ulonglong2*)&Bs[kk * 132 + tc])[0];
                    bvv[0] = q0.x; bvv[1] = q0.y;
                    if (TN == 8) {
                        ulonglong2 q1 = ((const ulonglong2*)&Bs[kk * 132 + tc])[1];
                        bvv[2] = q1.x; bvv[3] = q1.y;
                    }
                }
#pragma unroll
                for (int i = 0; i < 8; i++)
#pragma unroll
                    for (int j = 0; j < TN / 2; j++) ffma2(acc[i][j], av[i], bvv[j]);
            }
        }
#pragma unroll
        for (int i = 0; i < 8; i++) {
            int r = m0 + tr + i;
            if (r >= M) continue;
            int c = r >> 4, b = r & 15;
#pragma unroll
            for (int j = 0; j < TN / 2; j++) {
                float2 v = unpk(acc[i][j]);
                int col = n0 + tc + 2 * j;
                if (col < NC) {
                    int s = col / 500, w = col - s * 500;
                    Out[(s * CCH + c) * BN + b * 500 + w] = v.x;
                }
                if (col + 1 < NC) {
                    int s2 = (col + 1) / 500, w2 = (col + 1) - s2 * 500;
                    Out[(s2 * CCH + c) * BN + b * 500 + w2] = v.y;
                }
            }
        }
    }
}

// ---------- A^2 (setup) ----------
__device__ __forceinline__ void sq_tiles(const float* __restrict__ Af,
                                         const float* __restrict__ Ab, float* sm) {
    float* As = sm;             // [16][68]
    float* Bq = sm + 16 * 68;
    const int tid = threadIdx.x;
    for (int tile = blockIdx.x; tile < 128; tile += NBLK) {
        const float* A = (tile < 64) ? Af : Ab;
        const int dst = (tile < 64) ? 250000 : 750000;
        const int tt = tile & 63;
        const int m0 = (tt >> 3) * 64, n0 = (tt & 7) * 64;
        const int rg = (tid >> 4) * 4, cg = (tid & 15) * 4;
        float acc[4][4] = {};
        for (int k0 = 0; k0 < 500; k0 += 16) {
            __syncthreads();
#pragma unroll
            for (int q = 0; q < 4; q++) {
                int e = tid + q * 256;
                int r = e >> 4, kk = e & 15;
                float v = 0.f;
                int gr = m0 + r, gk = k0 + kk;
                if (gr < 500 && gk < 500) v = A[gr * 500 + gk];
                As[kk * 68 + r] = v;
                int kb = e >> 6, j = e & 63;
                float w = 0.f;
                int gk2 = k0 + kb, gc = n0 + j;
                if (gk2 < 500 && gc < 500) w = A[gk2 * 500 + gc];
                Bq[kb * 68 + j] = w;
            }
            __syncthreads();
#pragma unroll
            for (int kk = 0; kk < 16; kk++) {
                float a[4], b[4];
#pragma unroll
                for (int i = 0; i < 4; i++) { a[i] = As[kk * 68 + rg + i]; b[i] = Bq[kk * 68 + cg + i]; }
#pragma unroll
                for (int i = 0; i < 4; i++)
#pragma unroll
                    for (int j = 0; j < 4; j++) acc[i][j] += a[i] * b[j];
            }
        }
#pragma unroll
        for (int i = 0; i < 4; i++) {
            int r = m0 + rg + i;
            if (r >= 500) continue;
#pragma unroll
            for (int j = 0; j < 4; j++) {
                int c = n0 + cg + j;
                if (c < 500) g_M4[dst + r * 500 + c] = acc[i][j];
            }
        }
    }
}

// ---------- the single persistent kernel ----------
__global__ void __launch_bounds__(256, 1) gril_persist(
    const float* __restrict__ x, const float* __restrict__ Af, const float* __restrict__ Ab,
    const int* __restrict__ mask,
    const float* __restrict__ Wr, const float* __restrict__ br,
    const float* __restrict__ Wu, const float* __restrict__ bu,
    const float* __restrict__ Wc, const float* __restrict__ bc,
    const float* __restrict__ Wfs, const float* __restrict__ bfs,
    const float* __restrict__ Wli, const float* __restrict__ bli,
    const float* __restrict__ Wgc, const float* __restrict__ bgc,
    const float* __restrict__ Wlo, const float* __restrict__ blo,
    const float* __restrict__ Wro, const float* __restrict__ bro,
    const float* __restrict__ pa,
    float* __restrict__ imp, float* __restrict__ pred, float* __restrict__ reps) {
    __shared__ float sm[2176];
    __shared__ float sm_out[64 * 128];
    const int tid = threadIdx.x;
    const int gid0 = blockIdx.x * 256 + tid;
    const int gstr = NBLK * 256;

    // ---- setup ----
    for (int i = gid0; i < TT * BN; i += gstr) {
        int t = i & 127, bn = i >> 7;
        g_xT[t * BN + bn] = x[i];
        g_mT[t * BN + bn] = (float)mask[i];
    }
    for (int i = gid0; i < 250000; i += gstr) {
        float vf = Af[i], vb = Ab[i];
        g_M4[i] = vf; g_M4[500000 + i] = vb;
        g_M2[i] = vf; g_M2[250000 + i] = vb;
    }
    for (int i = gid0; i < 64 * BN; i += gstr) g_h[i] = 0.f;
    for (int i = gid0; i < 64 * 330; i += gstr) {
        int o = i / 330, j = i - o * 330;
        g_Wru[o * 330 + j] = Wr[i];
        g_Wru[(64 + o) * 330 + j] = Wu[i];
    }
    for (int i = gid0; i < 64 * 128; i += gstr) {
        int o = i >> 7, j = i & 127;
        float s = 0.f;
        for (int q = 0; q < 64; q++) s += Wlo[o * 128 + q] * Wgc[q * 128 + j];
        g_Wp[o * 192 + j] = s;
    }
    for (int i = gid0; i < 64 * 64; i += gstr) {
        int o = i >> 6, j = i & 63;
        g_Wp[o * 192 + 128 + j] = Wlo[o * 128 + 64 + j];
    }
    for (int i = gid0; i < 64; i += gstr) {
        float s = blo[i];
        for (int q = 0; q < 64; q++) s += Wlo[i * 128 + q] * bgc[q];
        g_bp[i] = s;
        g_bru[i] = br[i];
        g_bru[64 + i] = bu[i];
    }
    sq_tiles(Af, Ab, sm);
    gsync();

    // stage A at t=0 (h == 0)
    for (int bn = gid0; bn < BN; bn += gstr) {
        float acc = __ldg(bfs);
        pred[bn * TT] = acc;
        float m = g_mT[bn];
        g_x1[bn] = (m > 0.5f) ? g_xT[bn] : acc;
    }
    gsync();

    // ---- time loop ----
    for (int t = 0; t < TT; t++) {
        conv_stage<0, 0>(t, Wli, bli, sm, sm_out, 0, 0, 0, 0, 0, imp, pred, reps);
        gsync();
        diff_stage<0, 4>(t, sm);
        gsync();
        conv_stage<1, 1>(t, g_Wp, g_bp, sm, sm_out, Wro, bro, 0, 0, pa, imp, pred, reps);
        gsync();
        diff_stage<1, 8>(t, sm);
        gsync();
        conv_stage<2, 2>(t, g_Wru, g_bru, sm, sm_out, 0, 0, 0, 0, 0, imp, pred, reps);
        gsync();
        diff_stage<2, 8>(t, sm);
        gsync();
        conv_stage<3, 3>(t, Wc, bc, sm, sm_out, 0, 0, Wfs, bfs, 0, imp, pred, reps);
        gsync();
    }
}

// ---------- host: ONE kernel node ----------
extern "C" void kernel_launch(void* const* d_in, const int* in_sizes, int n_in,
                              void* d_out, int out_size) {
    const float* x    = (const float*)d_in[0];
    const float* Af   = (const float*)d_in[1];
    const float* Ab   = (const float*)d_in[2];
    const int*   mask = (const int*)  d_in[3];
    const float* Wr   = (const float*)d_in[4];
    const float* br   = (const float*)d_in[5];
    const float* Wu   = (const float*)d_in[6];
    const float* bu   = (const float*)d_in[7];
    const float* Wc   = (const float*)d_in[8];
    const float* bc   = (const float*)d_in[9];
    const float* Wfs  = (const float*)d_in[10];
    const float* bfs  = (const float*)d_in[11];
    const float* Wli  = (const float*)d_in[12];
    const float* bli  = (const float*)d_in[13];
    const float* Wgc  = (const float*)d_in[14];
    const float* bgc  = (const float*)d_in[15];
    const float* Wlo  = (const float*)d_in[16];
    const float* blo  = (const float*)d_in[17];
    const float* Wro  = (const float*)d_in[18];
    const float* bro  = (const float*)d_in[19];
    const float* pa   = (const float*)d_in[20];

    float* imp  = (float*)d_out;
    float* pred = imp + 16 * 500 * 128;
    float* reps = imp + 2 * 16 * 500 * 128;

    gril_persist<<<NBLK, 256>>>(x, Af, Ab, mask, Wr, br, Wu, bu, Wc, bc,
                                Wfs, bfs, Wli, bli, Wgc, bgc, Wlo, blo,
                                Wro, bro, pa, imp, pred, reps);
}

// round 4
// speedup vs baseline: 1.0135x; 1.0135x over previous
#include <cuda_runtime.h>
#include <math.h>

#define NBLK 148
#define BN   8000
#define TT   128
typedef unsigned long long ull;

// ---------- static device scratch ----------
__device__ float g_xT[TT * BN];
__device__ float g_mT[TT * BN];
__device__ float g_M4[2000 * 500];   // Af, Af^2, Ab, Ab^2
__device__ float g_M2[1000 * 500];   // Af, Ab
__device__ float g_h[64 * BN];
__device__ float g_xin[64 * BN];
__device__ float g_Ddec[128 * BN];
__device__ float g_rh[64 * BN];
__device__ float g_u[64 * BN];
__device__ float g_Dgd[264 * BN];
__device__ float g_Dcd[264 * BN];
__device__ float g_x1[BN];
__device__ float g_x2[BN];
__device__ float g_Wru[128 * 330];
__device__ float g_Wp[64 * 192];
__device__ float g_bru[128];
__device__ float g_bp[64];
__device__ unsigned g_cnt;
__device__ volatile unsigned g_gen;

// ---------- f32x2 helpers ----------
__device__ __forceinline__ ull splat2(float x) {
    ull r; asm("mov.b64 %0,{%1,%1};" : "=l"(r) : "f"(x)); return r;
}
__device__ __forceinline__ void ffma2(ull& d, ull a, ull b) {
    asm("fma.rn.f32x2 %0,%1,%2,%3;" : "=l"(d) : "l"(a), "l"(b), "l"(d));
}
__device__ __forceinline__ float2 unpk(ull p) {
    float2 v; asm("mov.b64 {%0,%1},%2;" : "=f"(v.x), "=f"(v.y) : "l"(p)); return v;
}

// ---------- software grid barrier ----------
__device__ __forceinline__ void gsync() {
    __syncthreads();
    if (threadIdx.x == 0) {
        __threadfence();
        unsigned gen = g_gen;
        if (atomicAdd(&g_cnt, 1u) == NBLK - 1) {
            atomicExch(&g_cnt, 0u);
            __threadfence();
            g_gen = gen + 1;
        } else {
            while (g_gen == gen) __nanosleep(32);
        }
        __threadfence();   // IVALL: invalidate this SM's L1 before CTA proceeds
    }
    __syncthreads();
}

// ---------- conv input channel dispatch ----------
template <int KIND>
__device__ __forceinline__ const float* conv_in(int k, int t) {
    if (KIND == 0) {                       // [x1, mf, h]  K=66
        if (k == 0) return g_x1;
        if (k == 1) return g_mT + t * BN;
        return g_h + (k - 2) * BN;
    } else if (KIND == 1) {                // [Ddec(128), h]  K=192
        return (k < 128) ? g_Ddec + k * BN : g_h + (k - 128) * BN;
    } else if (KIND == 2) {                // [x2, mf, h, Dgd]  K=330
        if (k == 0) return g_x2;
        if (k == 1) return g_mT + t * BN;
        if (k < 66) return g_h + (k - 2) * BN;
        return g_Dgd + (k - 66) * BN;
    } else {                               // [x2, mf, rh, Dcd]  K=330
        if (k == 0) return g_x2;
        if (k == 1) return g_mT + t * BN;
        if (k < 66) return g_rh + (k - 2) * BN;
        return g_Dcd + (k - 66) * BN;
    }
}

// ---------- fused stage B (after W_p tile; out tile in sm_out) ----------
__device__ __forceinline__ void stageB_tile(int t, int n0, float* sm, const float* sm_out,
        const float* __restrict__ Wro, const float* __restrict__ bro,
        float* __restrict__ imp, float* __restrict__ reps) {
    int tid = threadIdx.x;
    __syncthreads();
    if (tid < 128) sm[tid] = __ldg(Wro + tid);
    __syncthreads();
    if (tid < 128) {
        int bn = n0 + tid;
        if (bn < BN) {
            float acc = __ldg(bro);
            int b = bn / 500, n = bn - b * 500;
            int rbase = (b * 128 * 500 + n) * 128 + t;
#pragma unroll 4
            for (int c = 0; c < 64; c++) {
                float ov = sm_out[c * 128 + tid];
                float hv = g_h[c * BN + bn];
                acc += sm[c] * ov + sm[64 + c] * hv;
                reps[rbase + c * 64000] = ov;
                reps[rbase + (64 + c) * 64000] = hv;
            }
            imp[bn * TT + t] = acc;
            float m = g_mT[t * BN + bn];
            g_x2[bn] = (m > 0.5f) ? g_x1[bn] : acc;
        }
    }
}

// ---------- fused stage A for t=tn (new-h tile in sm_out) ----------
__device__ __forceinline__ void stageA_tile(int tn, int n0, float* sm, const float* sm_out,
        const float* __restrict__ Wfs, const float* __restrict__ bfs,
        float* __restrict__ pred) {
    int tid = threadIdx.x;
    __syncthreads();
    if (tid < 64) sm[tid] = __ldg(Wfs + tid);
    __syncthreads();
    if (tid < 128) {
        int bn = n0 + tid;
        if (bn < BN) {
            float acc = __ldg(bfs);
#pragma unroll 8
            for (int c = 0; c < 64; c++) acc += sm[c] * sm_out[c * 128 + tid];
            pred[bn * TT + tn] = acc;
            float m = g_mT[tn * BN + bn];
            g_x1[bn] = (m > 0.5f) ? g_xT[tn * BN + bn] : acc;
        }
    }
}

// ---------- conv GEMM stage (O x 8000), fused epilogues ----------
// EPI 0:->g_xin  1: prelu->sm_out + stageB  2: sigmoid->rh/u  3: tanh+GRU->h + stageA
template <int KIND, int EPI>
__device__ __forceinline__ void conv_stage(int t,
        const float* __restrict__ Wg, const float* __restrict__ bias,
        float* sm, float* sm_out,
        const float* Wro, const float* bro,
        const float* Wfs, const float* bfs, const float* pa,
        float* imp, float* pred, float* reps) {
    constexpr int K = (KIND == 0) ? 66 : (KIND == 1) ? 192 : 330;
    constexpr int NOROW = (KIND == 2) ? 2 : 1;
    float* Ws = sm;            // [8][68]
    float* Is = sm + 8 * 68;   // [8][132]
    const int tid = threadIdx.x;
    for (int tile = blockIdx.x; tile < NOROW * 63; tile += NBLK) {
        const int o0 = (tile / 63) * 64;
        const int n0 = (tile % 63) * 128;
        const int rg = (tid >> 4) * 4;
        const int cg = (tid & 15) * 8;
        ull acc[4][4];
#pragma unroll
        for (int i = 0; i < 4; i++)
#pragma unroll
            for (int j = 0; j < 4; j++) acc[i][j] = 0ull;

        float wv0, wv1; float4 iv;
        {
            int e0 = tid, e1 = tid + 256;
            int kg0 = e0 & 7, kg1 = e1 & 7;
            wv0 = (kg0 < K) ? __ldg(Wg + (o0 + (e0 >> 3)) * K + kg0) : 0.f;
            wv1 = (kg1 < K) ? __ldg(Wg + (o0 + (e1 >> 3)) * K + kg1) : 0.f;
            int kk = tid >> 5, j4 = (tid & 31) * 4, col = n0 + j4;
            iv = make_float4(0.f, 0.f, 0.f, 0.f);
            if (kk < K && col < BN) iv = *(const float4*)(conv_in<KIND>(kk, t) + col);
        }
        for (int k0 = 0; k0 < K; k0 += 8) {
            __syncthreads();
            {
                int e0 = tid, e1 = tid + 256;
                Ws[(e0 & 7) * 68 + (e0 >> 3)] = wv0;
                Ws[(e1 & 7) * 68 + (e1 >> 3)] = wv1;
                int kk = tid >> 5, j4 = (tid & 31) * 4;
                *(float4*)&Is[kk * 132 + j4] = iv;
            }
            __syncthreads();
            if (k0 + 8 < K) {
                int e0 = tid, e1 = tid + 256;
                int kg0 = k0 + 8 + (e0 & 7), kg1 = k0 + 8 + (e1 & 7);
                wv0 = (kg0 < K) ? __ldg(Wg + (o0 + (e0 >> 3)) * K + kg0) : 0.f;
                wv1 = (kg1 < K) ? __ldg(Wg + (o0 + (e1 >> 3)) * K + kg1) : 0.f;
                int kk = tid >> 5, j4 = (tid & 31) * 4, col = n0 + j4;
                int kg = k0 + 8 + kk;
                iv = make_float4(0.f, 0.f, 0.f, 0.f);
                if (kg < K && col < BN) iv = *(const float4*)(conv_in<KIND>(kg, t) + col);
            }
#pragma unroll
            for (int kk = 0; kk < 8; kk++) {
                float4 a = *(const float4*)&Ws[kk * 68 + rg];
                ull av0 = splat2(a.x), av1 = splat2(a.y), av2 = splat2(a.z), av3 = splat2(a.w);
                ulonglong2 q0 = ((const ulonglong2*)&Is[kk * 132 + cg])[0];
                ulonglong2 q1 = ((const ulonglong2*)&Is[kk * 132 + cg])[1];
                ffma2(acc[0][0], av0, q0.x); ffma2(acc[0][1], av0, q0.y);
                ffma2(acc[0][2], av0, q1.x); ffma2(acc[0][3], av0, q1.y);
                ffma2(acc[1][0], av1, q0.x); ffma2(acc[1][1], av1, q0.y);
                ffma2(acc[1][2], av1, q1.x); ffma2(acc[1][3], av1, q1.y);
                ffma2(acc[2][0], av2, q0.x); ffma2(acc[2][1], av2, q0.y);
                ffma2(acc[2][2], av2, q1.x); ffma2(acc[2][3], av2, q1.y);
                ffma2(acc[3][0], av3, q0.x); ffma2(acc[3][1], av3, q0.y);
                ffma2(acc[3][2], av3, q1.x); ffma2(acc[3][3], av3, q1.y);
            }
        }
        float paval = (EPI == 1) ? __ldg(pa) : 0.f;
#pragma unroll
        for (int i = 0; i < 4; i++) {
            int o = o0 + rg + i;
            float bs = __ldg(bias + o);
#pragma unroll
            for (int j2 = 0; j2 < 4; j2++) {
                float2 v2 = unpk(acc[i][j2]);
#pragma unroll
                for (int e = 0; e < 2; e++) {
                    int bn = n0 + cg + 2 * j2 + e;
                    if (bn >= BN) continue;
                    float v = ((e == 0) ? v2.x : v2.y) + bs;
                    if (EPI == 0) {
                        g_xin[o * BN + bn] = v;
                    } else if (EPI == 1) {
                        sm_out[o * 128 + (bn - n0)] = (v >= 0.f) ? v : paval * v;
                    } else if (EPI == 2) {
                        float sv = 1.f / (1.f + expf(-v));
                        if (o < 64) g_rh[o * BN + bn] = sv * g_h[o * BN + bn];
                        else        g_u[(o - 64) * BN + bn] = sv;
                    } else {
                        float cv = tanhf(v);
                        int id = o * BN + bn;
                        float uu = g_u[id];
                        float hn = uu * g_h[id] + (1.f - uu) * cv;
                        g_h[id] = hn;
                        sm_out[o * 128 + (bn - n0)] = hn;
                    }
                }
            }
        }
        if (EPI == 1) stageB_tile(t, n0, sm, sm_out, Wro, bro, imp, reps);
        if (EPI == 3 && t + 1 < TT) stageA_tile(t + 1, n0, sm, sm_out, Wfs, bfs, pred);
    }
}

// ---------- diffusion GEMM: rows x Ncols, K=500 ----------
// KIND 0: X=g_xin (M=1024), B=g_M2, N=1000 -> g_Ddec
// KIND 1: X=[x2,mf,h] (M=1056), B=g_M4, N=2000 -> g_Dgd
// KIND 2: X=[x2,mf,rh] -> g_Dcd
template <int KIND, int TN>
__device__ __forceinline__ void diff_stage(int t, float* sm) {
    constexpr int M   = (KIND == 0) ? 1024 : 1056;
    constexpr int NC  = (KIND == 0) ? 1000 : 2000;
    constexpr int CCH = (KIND == 0) ? 64 : 66;
    constexpr int BC  = TN * 16;
    constexpr int TM  = (M + 127) / 128;
    constexpr int TNC = (NC + BC - 1) / BC;
    const float* Bm = (KIND == 0) ? g_M2 : g_M4;
    float* Out = (KIND == 0) ? g_Ddec : ((KIND == 1) ? g_Dgd : g_Dcd);
    float* Xs = sm;            // [8][132]
    float* Bs = sm + 8 * 132;
    const int tid = threadIdx.x;
    for (int tile = blockIdx.x; tile < TM * TNC; tile += NBLK) {
        const int m0 = (tile / TNC) * 128;
        const int n0 = (tile % TNC) * BC;
        const int lr = tid >> 1, lk = (tid & 1) * 4;
        const float* xrow = nullptr;
        {
            int gr = m0 + lr;
            if (gr < M) {
                if (KIND == 0) {
                    xrow = g_xin + gr * 500;   // [c][b][n] == gr*500
                } else {
                    int c = gr >> 4, b = gr & 15;
                    const float* base = (c == 0) ? g_x2
                                       : (c == 1) ? (g_mT + t * BN)
                                       : (((KIND == 1) ? g_h : g_rh) + (c - 2) * BN);
                    xrow = base + b * 500;
                }
            }
        }
        const float* brow = nullptr;
        if (lr < BC) { int gc = n0 + lr; if (gc < NC) brow = Bm + gc * 500; }
        const int tr = (tid >> 4) * 8;
        const int tc = (tid & 15) * TN;
        ull acc[8][TN / 2];
#pragma unroll
        for (int i = 0; i < 8; i++)
#pragma unroll
            for (int j = 0; j < TN / 2; j++) acc[i][j] = 0ull;

        float4 xv = make_float4(0.f, 0.f, 0.f, 0.f), bv = xv;
        if (xrow) xv = *(const float4*)(xrow + lk);
        if (brow) bv = *(const float4*)(brow + lk);
        for (int k0 = 0; k0 < 500; k0 += 8) {
            __syncthreads();
            Xs[(lk + 0) * 132 + lr] = xv.x; Xs[(lk + 1) * 132 + lr] = xv.y;
            Xs[(lk + 2) * 132 + lr] = xv.z; Xs[(lk + 3) * 132 + lr] = xv.w;
            if (lr < BC) {
                Bs[(lk + 0) * 132 + lr] = bv.x; Bs[(lk + 1) * 132 + lr] = bv.y;
                Bs[(lk + 2) * 132 + lr] = bv.z; Bs[(lk + 3) * 132 + lr] = bv.w;
            }
            __syncthreads();
            if (k0 + 8 < 500) {
                int kn = k0 + 8 + lk;
                xv = make_float4(0.f, 0.f, 0.f, 0.f); bv = xv;
                if (xrow && kn < 500) {
                    if (kn + 3 < 500) xv = *(const float4*)(xrow + kn);
                    else { xv.x = xrow[kn]; if (kn+1<500) xv.y = xrow[kn+1];
                           if (kn+2<500) xv.z = xrow[kn+2]; }
                }
                if (brow && kn < 500) {
                    if (kn + 3 < 500) bv = *(const float4*)(brow + kn);
                    else { bv.x = brow[kn]; if (kn+1<500) bv.y = brow[kn+1];
                           if (kn+2<500) bv.z = brow[kn+2]; }
                }
            }
#pragma unroll
            for (int kk = 0; kk < 8; kk++) {
                float4 a0 = *(const float4*)&Xs[kk * 132 + tr];
                float4 a1 = *(const float4*)&Xs[kk * 132 + tr + 4];
                ull av[8] = {splat2(a0.x), splat2(a0.y), splat2(a0.z), splat2(a0.w),
                             splat2(a1.x), splat2(a1.y), splat2(a1.z), splat2(a1.w)};
                ull bvv[TN / 2];
                {
                    ulonglong2 q0 = ((const ulonglong2*)&Bs[kk * 132 + tc])[0];
                    bvv[0] = q0.x; bvv[1] = q0.y;
                    if (TN == 8) {
                        ulonglong2 q1 = ((const ulonglong2*)&Bs[kk * 132 + tc])[1];
                        bvv[2] = q1.x; bvv[3] = q1.y;
                    }
                }
#pragma unroll
                for (int i = 0; i < 8; i++)
#pragma unroll
                    for (int j = 0; j < TN / 2; j++) ffma2(acc[i][j], av[i], bvv[j]);
            }
        }
#pragma unroll
        for (int i = 0; i < 8; i++) {
            int r = m0 + tr + i;
            if (r >= M) continue;
            int c = r >> 4, b = r & 15;
#pragma unroll
            for (int j = 0; j < TN / 2; j++) {
                float2 v = unpk(acc[i][j]);
                int col = n0 + tc + 2 * j;
                if (col < NC) {
                    int s = col / 500, w = col - s * 500;
                    Out[(s * CCH + c) * BN + b * 500 + w] = v.x;
                }
                if (col + 1 < NC) {
                    int s2 = (col + 1) / 500, w2 = (col + 1) - s2 * 500;
                    Out[(s2 * CCH + c) * BN + b * 500 + w2] = v.y;
                }
            }
        }
    }
}

// ---------- A^2 (setup) ----------
__device__ __forceinline__ void sq_tiles(const float* __restrict__ Af,
                                         const float* __restrict__ Ab, float* sm) {
    float* As = sm;             // [16][68]
    float* Bq = sm + 16 * 68;
    const int tid = threadIdx.x;
    for (int tile = blockIdx.x; tile < 128; tile += NBLK) {
        const float* A = (tile < 64) ? Af : Ab;
        const int dst = (tile < 64) ? 250000 : 750000;
        const int tt = tile & 63;
        const int m0 = (tt >> 3) * 64, n0 = (tt & 7) * 64;
        const int rg = (tid >> 4) * 4, cg = (tid & 15) * 4;
        float acc[4][4] = {};
        for (int k0 = 0; k0 < 500; k0 += 16) {
            __syncthreads();
#pragma unroll
            for (int q = 0; q < 4; q++) {
                int e = tid + q * 256;
                int r = e >> 4, kk = e & 15;
                float v = 0.f;
                int gr = m0 + r, gk = k0 + kk;
                if (gr < 500 && gk < 500) v = A[gr * 500 + gk];
                As[kk * 68 + r] = v;
                int kb = e >> 6, j = e & 63;
                float w = 0.f;
                int gk2 = k0 + kb, gc = n0 + j;
                if (gk2 < 500 && gc < 500) w = A[gk2 * 500 + gc];
                Bq[kb * 68 + j] = w;
            }
            __syncthreads();
#pragma unroll
            for (int kk = 0; kk < 16; kk++) {
                float a[4], b[4];
#pragma unroll
                for (int i = 0; i < 4; i++) { a[i] = As[kk * 68 + rg + i]; b[i] = Bq[kk * 68 + cg + i]; }
#pragma unroll
                for (int i = 0; i < 4; i++)
#pragma unroll
                    for (int j = 0; j < 4; j++) acc[i][j] += a[i] * b[j];
            }
        }
#pragma unroll
        for (int i = 0; i < 4; i++) {
            int r = m0 + rg + i;
            if (r >= 500) continue;
#pragma unroll
            for (int j = 0; j < 4; j++) {
                int c = n0 + cg + j;
                if (c < 500) g_M4[dst + r * 500 + c] = acc[i][j];
            }
        }
    }
}

// ---------- the single persistent kernel ----------
__global__ void __launch_bounds__(256, 1) gril_persist(
    const float* __restrict__ x, const float* __restrict__ Af, const float* __restrict__ Ab,
    const int* __restrict__ mask,
    const float* __restrict__ Wr, const float* __restrict__ br,
    const float* __restrict__ Wu, const float* __restrict__ bu,
    const float* __restrict__ Wc, const float* __restrict__ bc,
    const float* __restrict__ Wfs, const float* __restrict__ bfs,
    const float* __restrict__ Wli, const float* __restrict__ bli,
    const float* __restrict__ Wgc, const float* __restrict__ bgc,
    const float* __restrict__ Wlo, const float* __restrict__ blo,
    const float* __restrict__ Wro, const float* __restrict__ bro,
    const float* __restrict__ pa,
    float* __restrict__ imp, float* __restrict__ pred, float* __restrict__ reps) {
    __shared__ float sm[2176];
    __shared__ float sm_out[64 * 128];
    const int tid = threadIdx.x;
    const int gid0 = blockIdx.x * 256 + tid;
    const int gstr = NBLK * 256;

    // ---- setup ----
    for (int i = gid0; i < TT * BN; i += gstr) {
        int t = i & 127, bn = i >> 7;
        g_xT[t * BN + bn] = x[i];
        g_mT[t * BN + bn] = (float)mask[i];
    }
    for (int i = gid0; i < 250000; i += gstr) {
        float vf = Af[i], vb = Ab[i];
        g_M4[i] = vf; g_M4[500000 + i] = vb;
        g_M2[i] = vf; g_M2[250000 + i] = vb;
    }
    for (int i = gid0; i < 64 * BN; i += gstr) g_h[i] = 0.f;
    for (int i = gid0; i < 64 * 330; i += gstr) {
        int o = i / 330, j = i - o * 330;
        g_Wru[o * 330 + j] = Wr[i];
        g_Wru[(64 + o) * 330 + j] = Wu[i];
    }
    for (int i = gid0; i < 64 * 128; i += gstr) {
        int o = i >> 7, j = i & 127;
        float s = 0.f;
        for (int q = 0; q < 64; q++) s += Wlo[o * 128 + q] * Wgc[q * 128 + j];
        g_Wp[o * 192 + j] = s;
    }
    for (int i = gid0; i < 64 * 64; i += gstr) {
        int o = i >> 6, j = i & 63;
        g_Wp[o * 192 + 128 + j] = Wlo[o * 128 + 64 + j];
    }
    for (int i = gid0; i < 64; i += gstr) {
        float s = blo[i];
        for (int q = 0; q < 64; q++) s += Wlo[i * 128 + q] * bgc[q];
        g_bp[i] = s;
        g_bru[i] = br[i];
        g_bru[64 + i] = bu[i];
    }
    sq_tiles(Af, Ab, sm);
    gsync();

    // stage A at t=0 (h == 0)
    for (int bn = gid0; bn < BN; bn += gstr) {
        float acc = __ldg(bfs);
        pred[bn * TT] = acc;
        float m = g_mT[bn];
        g_x1[bn] = (m > 0.5f) ? g_xT[bn] : acc;
    }
    gsync();

    // ---- time loop ----
    for (int t = 0; t < TT; t++) {
        conv_stage<0, 0>(t, Wli, bli, sm, sm_out, 0, 0, 0, 0, 0, imp, pred, reps);
        gsync();
        diff_stage<0, 4>(t, sm);
        gsync();
        conv_stage<1, 1>(t, g_Wp, g_bp, sm, sm_out, Wro, bro, 0, 0, pa, imp, pred, reps);
        gsync();
        diff_stage<1, 8>(t, sm);
        gsync();
        conv_stage<2, 2>(t, g_Wru, g_bru, sm, sm_out, 0, 0, 0, 0, 0, imp, pred, reps);
        gsync();
        diff_stage<2, 8>(t, sm);
        gsync();
        conv_stage<3, 3>(t, Wc, bc, sm, sm_out, 0, 0, Wfs, bfs, 0, imp, pred, reps);
        gsync();
    }
}

// ---------- host: ONE kernel node ----------
extern "C" void kernel_launch(void* const* d_in, const int* in_sizes, int n_in,
                              void* d_out, int out_size) {
    const float* x    = (const float*)d_in[0];
    const float* Af   = (const float*)d_in[1];
    const float* Ab   = (const float*)d_in[2];
    const int*   mask = (const int*)  d_in[3];
    const float* Wr   = (const float*)d_in[4];
    const float* br   = (const float*)d_in[5];
    const float* Wu   = (const float*)d_in[6];
    const float* bu   = (const float*)d_in[7];
    const float* Wc   = (const float*)d_in[8];
    const float* bc   = (const float*)d_in[9];
    const float* Wfs  = (const float*)d_in[10];
    const float* bfs  = (const float*)d_in[11];
    const float* Wli  = (const float*)d_in[12];
    const float* bli  = (const float*)d_in[13];
    const float* Wgc  = (const float*)d_in[14];
    const float* bgc  = (const float*)d_in[15];
    const float* Wlo  = (const float*)d_in[16];
    const float* blo  = (const float*)d_in[17];
    const float* Wro  = (const float*)d_in[18];
    const float* bro  = (const float*)d_in[19];
    const float* pa   = (const float*)d_in[20];

    float* imp  = (float*)d_out;
    float* pred = imp + 16 * 500 * 128;
    float* reps = imp + 2 * 16 * 500 * 128;

    gril_persist<<<NBLK, 256>>>(x, Af, Ab, mask, Wr, br, Wu, bu, Wc, bc,
                                Wfs, bfs, Wli, bli, Wgc, bgc, Wlo, blo,
                                Wro, bro, pa, imp, pred, reps);
}